// round 15
// baseline (speedup 1.0000x reference)
#include <cuda_runtime.h>
#include <math.h>

#define BB 2
#define HH 384
#define WW 512
#define NN (HH*WW)          // 196608 pixels
#define BBNN (BB*NN)
#define TT (1<<20)
#define TMASK (TT-1)
#define H1 192
#define W1 256
#define H2 96
#define W2 128
#define MAXG 1024

// ------------------------- device scratch -------------------------
__device__ float d_x1[BB*16*H1*W1];
__device__ float d_x2[BB*16*H2*W2];
__device__ float d_dx1[BB*16*H2*W2];
__device__ float d_catb[BB*32*H1*W1];
__device__ float d_dx2[BB*16*H1*W1];
__device__ float d_dx2up[BB*16*NN];
__device__ float d_conf[BB*NN];

__device__ unsigned d_simgU[BB];
__device__ unsigned d_sfeatU[BB];
__device__ unsigned d_cmaxU;
__device__ double   d_gnS[4][8];

__device__ int       d_pixh[BB*NN];
__device__ int       d_pixa[BB*NN];
__device__ long long d_pixkey[BB*NN];
__device__ int       d_winner[BB*TT];
__device__ unsigned long long d_ctabP[BB*TT];
__device__ int       d_cell2act[BB*TT];
__device__ int       d_actcell[BB*NN];
__device__ int       d_Mcnt[BB];
__device__ int       d_bc0[MAXG];
__device__ int       d_bc1[MAXG];
// SoA: [k][cellbase]
__device__ int       d_nbr[10*BBNN];
__device__ float     d_ew[10*BBNN];

__device__ float  d_cnt[BB*NN];
__device__ float  d_ws[BB*NN];
__device__ float  d_nA[BB*NN];
__device__ float  d_nB[BB*NN];
__device__ float  d_diag[BB*NN];
__device__ float  d_minv[BB*NN];
__device__ float4 d_b4[BB*NN];
__device__ float4 d_x4[BB*NN];
__device__ float4 d_r4[BB*NN];
__device__ float4 d_z4[BB*NN];
__device__ float4 d_p4[BB*NN];
__device__ float4 d_Ap4[BB*NN];

__device__ double d_rzS[13][8];
__device__ double d_papS[12][8];

// barrier state (self-cleaning across graph replays)
__device__ unsigned d_sub[8];
__device__ unsigned d_root;
__device__ volatile unsigned d_phase;

// ------------------------- helpers -------------------------
__device__ __forceinline__ void gridbar(){
    __syncthreads();
    if(threadIdx.x==0){
        __threadfence();
        unsigned gen = d_phase;
        unsigned G = gridDim.x;
        unsigned g = blockIdx.x & 7u;
        unsigned gsz = (G - g + 7u) >> 3;
        unsigned t = atomicInc(&d_sub[g], gsz-1u);
        if(t == gsz-1u){
            unsigned r = atomicInc(&d_root, 7u);
            if(r == 7u){
                __threadfence();
                d_phase = gen+1u;
            }
        }
        while(d_phase == gen){ __nanosleep(64); }
    }
    __syncthreads();
    __threadfence();
}

__device__ __forceinline__ void slotAdd8f(const float* acc, double* slot){
    __shared__ float s8[16][8];
    int wp=threadIdx.x>>5, ln=threadIdx.x&31;
#pragma unroll
    for(int c=0;c<8;c++){
        float v=acc[c];
        for(int off=16;off;off>>=1) v+=__shfl_down_sync(0xffffffffu,v,off);
        if(ln==0) s8[wp][c]=v;
    }
    __syncthreads();
    if(threadIdx.x<8){
        double s=0; int nw=blockDim.x>>5;
        for(int w=0;w<nw;w++) s+=(double)s8[w][threadIdx.x];
        atomicAdd(&slot[threadIdx.x], s);
    }
    __syncthreads();
}

__device__ __forceinline__ void slotAdd6f(const float* acc, double* slot){
    __shared__ float s6[16][6];
    int wp=threadIdx.x>>5, ln=threadIdx.x&31;
#pragma unroll
    for(int c=0;c<6;c++){
        float v=acc[c];
        for(int off=16;off;off>>=1) v+=__shfl_down_sync(0xffffffffu,v,off);
        if(ln==0) s6[wp][c]=v;
    }
    __syncthreads();
    if(threadIdx.x<6){
        double s=0; int nw=blockDim.x>>5;
        for(int w=0;w<nw;w++) s+=(double)s6[w][threadIdx.x];
        atomicAdd(&slot[threadIdx.x], s);
    }
    __syncthreads();
}

__device__ __forceinline__ void blockMaxAtomic(float v, unsigned* slot){
    __shared__ float sm[16];
    int wp=threadIdx.x>>5, ln=threadIdx.x&31;
    for(int off=16;off;off>>=1) v=fmaxf(v,__shfl_down_sync(0xffffffffu,v,off));
    if(ln==0) sm[wp]=v;
    __syncthreads();
    if(threadIdx.x==0){
        float m=0.f; int nw=blockDim.x>>5;
        for(int w=0;w<nw;w++) m=fmaxf(m,sm[w]);
        atomicMax(slot, __float_as_uint(m));
    }
    __syncthreads();
}

__device__ __forceinline__ void prep_gn(int layer,int HW,const float* __restrict__ gam,
                                        const float* __restrict__ bet,float* s_misc,int off){
    if(threadIdx.x<4){
        double s=d_gnS[layer][threadIdx.x*2], q=d_gnS[layer][threadIdx.x*2+1];
        double n=8.0*(double)HW;
        double mean=s/n, var=q/n-mean*mean;
        s_misc[off+threadIdx.x]=(float)mean;
        s_misc[off+4+threadIdx.x]=(float)(1.0/sqrt(var+1e-5));
    }
    if(threadIdx.x>=32&&threadIdx.x<48) s_misc[off+8+(threadIdx.x-32)]=gam[threadIdx.x-32];
    if(threadIdx.x>=64&&threadIdx.x<80) s_misc[off+24+(threadIdx.x-64)]=bet[threadIdx.x-64];
}

__device__ __forceinline__ float gn_apply(float raw,int b,int c,const float* s_misc,int off){
    int grp=b*2+(c>>3);
    float v=(raw-s_misc[off+grp])*s_misc[off+4+grp]*s_misc[off+8+c]+s_misc[off+24+c];
    return fmaxf(v,0.0f);
}

template<int INMODE,int IC>
__device__ __forceinline__ float rd(const float* __restrict__ in,
                                    const float* __restrict__ image,
                                    const float* __restrict__ pred,
                                    const float* s_misc,int b,int c,int iy,int ix,int IH,int IW){
    if(INMODE==1){
        size_t off=((size_t)(b*3+(c%3))*IH+iy)*IW+ix;
        return (c<3)? image[off]/s_misc[80+b] : pred[off];
    }
    float raw=in[((size_t)(b*IC+c)*IH+iy)*IW+ix];
    if(INMODE==2) return gn_apply(raw,b,c,s_misc,0);
    return raw;
}

// conv phase: 1 pixel × OCB output channels per item; fp32 GN partials
template<int IC,int OC,int OCB,int K,int S,bool EDGE,int INMODE,int GNIN,int GNOUT>
__device__ void conv_ph(const float* __restrict__ in,const float* __restrict__ image,
                        const float* __restrict__ pred,
                        int IH,int IW,int OH,int OW,
                        const float* __restrict__ wt,const float* __restrict__ bias,
                        int inHW,const float* __restrict__ gamIn,const float* __restrict__ betIn,
                        float* __restrict__ outp,
                        float* s_wt,float* s_misc,int T,int tid){
    if(INMODE==2) prep_gn(GNIN,inHW,gamIn,betIn,s_misc,0);
    if(INMODE==1){
        if(threadIdx.x<BB){
            float m=__uint_as_float(d_simgU[threadIdx.x]);
            s_misc[80+threadIdx.x]=fminf(fmaxf(m,1e-5f),1.0f);
        }
    }
    for(int i=threadIdx.x;i<OC*IC*K*K;i+=blockDim.x){
        int oc=i/(IC*K*K); int rest=i-oc*IC*K*K;
        s_wt[rest*OC+oc]=wt[i];
    }
    __syncthreads();

    float gacc[8]={0,0,0,0,0,0,0,0};
    const int NPX = BB*OH*OW;
    const int nog = OC/OCB;
    for(int idx=tid; idx<NPX*nog; idx+=T){
        int px = idx % NPX;
        int og = idx / NPX;
        int ox=px%OW; int r2=px/OW; int oy=r2%OH; int b=r2/OH;
        float a[OCB];
#pragma unroll
        for(int j=0;j<OCB;j++) a[j]=bias[og*OCB+j];
        for(int ic=0;ic<IC;ic++){
#pragma unroll
            for(int ky=0;ky<K;ky++){
                int iy=oy*S-1+ky;
                if(EDGE) iy=min(max(iy,0),IH-1);
                else if(iy<0||iy>=IH) continue;
#pragma unroll
                for(int kx=0;kx<K;kx++){
                    int ix=ox*S-1+kx;
                    float v;
                    if(EDGE){
                        int jx=min(max(ix,0),IW-1);
                        v=rd<INMODE,IC>(in,image,pred,s_misc,b,ic,iy,jx,IH,IW);
                    }else{
                        if(ix<0||ix>=IW) continue;
                        v=rd<INMODE,IC>(in,image,pred,s_misc,b,ic,iy,ix,IH,IW);
                    }
                    const float* w=&s_wt[((ic*K+ky)*K+kx)*OC + og*OCB];
#pragma unroll
                    for(int j=0;j<OCB;j++) a[j]=fmaf(v,w[j],a[j]);
                }
            }
        }
#pragma unroll
        for(int j=0;j<OCB;j++){
            int oc=og*OCB+j;
            outp[((size_t)(b*OC+oc)*OH+oy)*OW+ox]=a[j];
            if(GNOUT>=0){
                float dd=a[j];
                int slot=(b<<1)|(oc>>3);
                gacc[slot*2]+=dd; gacc[slot*2+1]+=dd*dd;
            }
        }
    }
    if(GNOUT>=0) slotAdd8f(gacc,d_gnS[GNOUT]);
}

__device__ __forceinline__ void pix_coords(const float* __restrict__ feature,int b,int pix,
                                           float s,int* c){
    float r  = (feature[(size_t)(b*3+0)*NN+pix]/s)*255.0f;
    float g  = (feature[(size_t)(b*3+1)*NN+pix]/s)*255.0f;
    float bl = (feature[(size_t)(b*3+2)*NN+pix]/s)*255.0f;
    int i = pix/WW, j = pix - i*WW;
    float Y = fmaf(bl,0.114f,    fmaf(g,0.587f,    r*0.299f));
    float U = fmaf(bl,0.5f,      fmaf(g,-0.331264f,r*(-0.168736f)))+128.0f;
    float V = fmaf(bl,-0.081312f,fmaf(g,-0.418688f,r*0.5f))+128.0f;
    c[0]=(int)floorf((float)j/7.0f);
    c[1]=(int)floorf((float)i/7.0f);
    c[2]=(int)floorf(Y*0.125f);
    c[3]=(int)floorf(U*0.5f);
    c[4]=(int)floorf(V*0.5f);
}

__device__ __forceinline__ int hash5i(const int* c){
    unsigned s = (unsigned)c[0]*73856093u + (unsigned)c[1]*19349663u + (unsigned)c[2]*83492791u
               + (unsigned)c[3]*49979687u + (unsigned)c[4]*24036583u;
    return (int)(s & (unsigned)TMASK);
}

__device__ __forceinline__ unsigned long long pack5(const int* c){
    unsigned long long k=0;
#pragma unroll
    for(int d=0;d<5;d++) k |= ((unsigned long long)(unsigned)(c[d]+1)) << (12*d);
    return k;
}

// ------------------------- THE kernel -------------------------
__global__ void __launch_bounds__(512,3) k_all(
    const float* __restrict__ image,const float* __restrict__ feature,const float* __restrict__ pred,
    const float* __restrict__ w1,const float* __restrict__ b1,const float* __restrict__ g1,const float* __restrict__ be1,
    const float* __restrict__ w2,const float* __restrict__ b2,const float* __restrict__ g2,const float* __restrict__ be2,
    const float* __restrict__ wd1,const float* __restrict__ bd1,const float* __restrict__ gd1,const float* __restrict__ bed1,
    const float* __restrict__ wd2,const float* __restrict__ bd2,const float* __restrict__ gd2,const float* __restrict__ bed2,
    const float* __restrict__ wf,const float* __restrict__ bf,
    float* __restrict__ out)
{
    const int T   = blockDim.x*gridDim.x;
    const int tid = blockIdx.x*blockDim.x + threadIdx.x;
    const int G   = gridDim.x;

    __shared__ float s_wt[4608];
    __shared__ float s_misc[128];
    __shared__ float s_alpha[6], s_beta[6];
    __shared__ int s_w0[16], s_w1[16];
    __shared__ int s_base0, s_base1, s_off0, s_off1, s_tot0, s_tot1;

    const unsigned PRIME[5]={73856093u,19349663u,83492791u,49979687u,24036583u};
    const int nsteps = (BBNN + G*512 - 1)/(G*512);
    const int chunk  = nsteps*512;

    // ================= P0: clears + input maxes (independent, fused) =================
    for(int i=tid;i<BB*TT;i+=T) d_winner[i]=-1;
    for(int i=tid;i<BB*TT;i+=T) d_ctabP[i]=0xFFFFFFFFFFFFFFFFULL;
    if(tid<BB) d_Mcnt[tid]=0;
    if(tid>=8 && tid<8+32)   ((double*)d_gnS)[tid-8]=0.0;
    if(tid>=64 && tid<64+104)((double*)d_rzS)[tid-64]=0.0;
    if(tid>=192 && tid<192+96)((double*)d_papS)[tid-192]=0.0;
    if(tid==300) d_cmaxU=0u;
    if(tid>=301&&tid<301+BB) d_simgU[tid-301]=0u;
    if(tid>=303&&tid<303+BB) d_sfeatU[tid-303]=0u;
    for(int i=tid;i<BB*NN;i+=T){
        d_cnt[i]=0.f; d_ws[i]=0.f;
        d_b4[i]=make_float4(0.f,0.f,0.f,0.f);
    }
    {
        float mi0=0.f,mi1=0.f,mf0=0.f,mf1=0.f;
        for(int i=tid;i<BB*3*NN;i+=T){
            float v=image[i], w=feature[i];
            if(i<3*NN){ mi0=fmaxf(mi0,v); mf0=fmaxf(mf0,w); }
            else      { mi1=fmaxf(mi1,v); mf1=fmaxf(mf1,w); }
        }
        blockMaxAtomic(mi0,&d_simgU[0]);
        blockMaxAtomic(mi1,&d_simgU[1]);
        blockMaxAtomic(mf0,&d_sfeatU[0]);
        blockMaxAtomic(mf1,&d_sfeatU[1]);
    }
    gridbar();

    // ================= P2: conv1 + hash =================
    conv_ph<6,16,4,4,2,true,1,0,0>(nullptr,image,pred,HH,WW,H1,W1,w1,b1,
                                   0,nullptr,nullptr,d_x1,s_wt,s_misc,T,tid);
    for(int w=tid;w<BB*NN;w+=T){
        int b=(w>=NN); int pix=w-(b?NN:0);
        float sf=fminf(fmaxf(__uint_as_float(d_sfeatU[b]),1e-5f),1.0f);
        int c[5]; pix_coords(feature,b,pix,sf,c);
        int h=hash5i(c);
        d_pixh[w]=h;
        d_pixkey[w]=(long long)pack5(c);
        atomicMax(&d_winner[b*TT+h],pix);
    }
    gridbar();

    // ================= P3: conv2 + ctab =================
    conv_ph<16,16,4,4,2,true,2,0,1>(d_x1,nullptr,nullptr,H1,W1,H2,W2,w2,b2,
                                    H1*W1,g1,be1,d_x2,s_wt,s_misc,T,tid);
    for(int w=tid;w<BB*NN;w+=T){
        int b=(w>=NN); int pix=w-(b?NN:0);
        int h=d_pixh[w];
        if(d_winner[b*TT+h]==pix)
            d_ctabP[b*TT+h]=(unsigned long long)d_pixkey[w];
    }
    gridbar();

    // ================= P4: convd1 + ordered-compact counts =================
    conv_ph<16,16,4,3,1,false,2,1,2>(d_x2,nullptr,nullptr,H2,W2,H2,W2,wd1,bd1,
                                     H2*W2,g2,be2,d_dx1,s_wt,s_misc,T,tid);
    {
        int start=blockIdx.x*chunk;
        int c0=0,c1=0;
        for(int o=threadIdx.x;o<chunk;o+=512){
            int w=start+o;
            if(w<BBNN){
                int b=(w>=NN); int pix=w-(b?NN:0);
                int h=d_pixh[w];
                if(d_winner[b*TT+h]==pix){ if(b) c1++; else c0++; }
            }
        }
        int wp=threadIdx.x>>5, ln=threadIdx.x&31;
        for(int off=16;off;off>>=1){
            c0+=__shfl_down_sync(0xffffffffu,c0,off);
            c1+=__shfl_down_sync(0xffffffffu,c1,off);
        }
        if(ln==0){ s_w0[wp]=c0; s_w1[wp]=c1; }
        __syncthreads();
        if(threadIdx.x==0){
            int t0=0,t1=0;
            for(int j=0;j<16;j++){ t0+=s_w0[j]; t1+=s_w1[j]; }
            d_bc0[blockIdx.x]=t0; d_bc1[blockIdx.x]=t1;
        }
        __syncthreads();
    }
    gridbar();

    // ================= P4b: ordered-compact assignment =================
    {
        int wp=threadIdx.x>>5, ln=threadIdx.x&31;
        if(wp==0){
            int o0=0,t0=0;
            for(int j=ln;j<G;j+=32){ int v=d_bc0[j]; t0+=v; if(j<blockIdx.x) o0+=v; }
            for(int off=16;off;off>>=1){
                o0+=__shfl_down_sync(0xffffffffu,o0,off);
                t0+=__shfl_down_sync(0xffffffffu,t0,off);
            }
            if(ln==0){ s_off0=o0; s_tot0=t0; }
        }
        if(wp==1){
            int o1=0,t1=0;
            for(int j=ln;j<G;j+=32){ int v=d_bc1[j]; t1+=v; if(j<blockIdx.x) o1+=v; }
            for(int off=16;off;off>>=1){
                o1+=__shfl_down_sync(0xffffffffu,o1,off);
                t1+=__shfl_down_sync(0xffffffffu,t1,off);
            }
            if(ln==0){ s_off1=o1; s_tot1=t1; }
        }
        __syncthreads();
        if(blockIdx.x==0&&threadIdx.x==0){ d_Mcnt[0]=s_tot0; d_Mcnt[1]=s_tot1; }
        if(threadIdx.x==0){ s_base0=s_off0; s_base1=s_off1; }
        __syncthreads();
        int start=blockIdx.x*chunk;
        for(int s=0;s<nsteps;s++){
            int w=start+s*512+threadIdx.x;
            int b=0,h=0; bool win=false;
            if(w<BBNN){
                b=(w>=NN); int pix=w-(b?NN:0);
                h=d_pixh[w];
                win=(d_winner[b*TT+h]==pix);
            }
            unsigned m0=__ballot_sync(0xffffffffu, win && b==0);
            unsigned m1=__ballot_sync(0xffffffffu, win && b==1);
            if(ln==0){ s_w0[wp]=__popc(m0); s_w1[wp]=__popc(m1); }
            __syncthreads();
            int p0=0,p1=0,tt0=0,tt1=0;
            for(int j=0;j<16;j++){
                int v0=s_w0[j], v1=s_w1[j];
                if(j<wp){ p0+=v0; p1+=v1; }
                tt0+=v0; tt1+=v1;
            }
            if(win){
                unsigned lm=(1u<<ln)-1u;
                int a = b? (s_base1+p1+__popc(m1&lm)) : (s_base0+p0+__popc(m0&lm));
                d_cell2act[b*TT+h]=a;
                d_actcell[b*NN+a]=h;
            }
            __syncthreads();
            if(threadIdx.x==0){ s_base0+=tt0; s_base1+=tt1; }
            __syncthreads();
        }
    }
    gridbar();

    // ================= P5: catb + nbr build (SoA) =================
    prep_gn(2,H2*W2,gd1,bed1,s_misc,0);
    prep_gn(0,H1*W1,g1,be1,s_misc,40);
    __syncthreads();
    for(int i=tid;i<BB*16*H1*W1;i+=T){
        int ox=i%W1; int r2=i/W1; int oy=r2%H1; r2/=H1;
        int c=r2%16; int b=r2/16;
        float cy=oy*0.5f-0.25f, cx=ox*0.5f-0.25f;
        int y0=(int)floorf(cy); float fy=cy-(float)y0;
        int x0=(int)floorf(cx); float fx=cx-(float)x0;
        int y1=min(y0+1,H2-1), x1=min(x0+1,W2-1);
        y0=max(y0,0); x0=max(x0,0);
        const float* ip=d_dx1+((size_t)(b*16+c))*H2*W2;
        float v00=gn_apply(ip[y0*W2+x0],b,c,s_misc,0);
        float v01=gn_apply(ip[y0*W2+x1],b,c,s_misc,0);
        float v10=gn_apply(ip[y1*W2+x0],b,c,s_misc,0);
        float v11=gn_apply(ip[y1*W2+x1],b,c,s_misc,0);
        float top=v00+fx*(v01-v00), bot=v10+fx*(v11-v10);
        d_catb[((size_t)(b*32+c)*H1+oy)*W1+ox]=top+fy*(bot-top);
    }
    for(int i=tid;i<BB*16*H1*W1;i+=T){
        int p=i%(H1*W1); int c=(i/(H1*W1))&15; int b=i/(16*H1*W1);
        float v=gn_apply(d_x1[((size_t)(b*16+c))*H1*W1+p],b,c,s_misc,40);
        d_catb[((size_t)(b*32+16+c))*H1*W1+p]=v;
    }
    for(int w=tid;w<BB*NN;w+=T){
        int b=(w>=NN); int a=w-(b?NN:0);
        if(a<d_Mcnt[b]){
            int cell=d_actcell[b*NN+a];
            unsigned long long key=d_ctabP[b*TT+cell];
            int base=b*NN+a;
            int k=0;
#pragma unroll
            for(int d=0;d<5;d++){
#pragma unroll
                for(int o=0;o<2;o++){
                    unsigned nh = ((unsigned)cell + (o? PRIME[d] : (0u-PRIME[d]))) & (unsigned)TMASK;
                    unsigned long long keyN = o? key+(1ULL<<(12*d)) : key-(1ULL<<(12*d));
                    int res=-1;
                    if(d_ctabP[b*TT+(int)nh]==keyN) res=d_cell2act[b*TT+(int)nh];
                    d_nbr[k*BBNN+base]=res;
                    k++;
                }
            }
            d_nA[base]=1.0f;
        }
    }
    gridbar();

    // ================= P6: convd2 =================
    conv_ph<32,16,4,3,1,false,0,0,3>(d_catb,nullptr,nullptr,H1,W1,H1,W1,wd2,bd2,
                                     0,nullptr,nullptr,d_dx2,s_wt,s_misc,T,tid);
    gridbar();

    // ================= P7: resize2 =================
    prep_gn(3,H1*W1,gd2,bed2,s_misc,0);
    __syncthreads();
    for(int i=tid;i<BB*16*NN;i+=T){
        int ox=i%WW; int r2=i/WW; int oy=r2%HH; r2/=HH;
        int c=r2%16; int b=r2/16;
        float cy=oy*0.5f-0.25f, cx=ox*0.5f-0.25f;
        int y0=(int)floorf(cy); float fy=cy-(float)y0;
        int x0=(int)floorf(cx); float fx=cx-(float)x0;
        int y1=min(y0+1,H1-1), x1=min(x0+1,W1-1);
        y0=max(y0,0); x0=max(x0,0);
        const float* ip=d_dx2+((size_t)(b*16+c))*H1*W1;
        float v00=gn_apply(ip[y0*W1+x0],b,c,s_misc,0);
        float v01=gn_apply(ip[y0*W1+x1],b,c,s_misc,0);
        float v10=gn_apply(ip[y1*W1+x0],b,c,s_misc,0);
        float v11=gn_apply(ip[y1*W1+x1],b,c,s_misc,0);
        float top=v00+fx*(v01-v00), bot=v10+fx*(v11-v10);
        d_dx2up[((size_t)(b*16+c)*HH+oy)*WW+ox]=top+fy*(bot-top);
    }
    gridbar();

    // ================= P8: convf + conf max + RAW splat (scaled later) =================
    for(int i=threadIdx.x;i<144;i+=blockDim.x) s_wt[i]=wf[i];
    __syncthreads();
    {
        float bias0=bf[0];
        float lmax=0.f;
        for(int idx=tid; idx<BB*NN; idx+=T){
            int ox=idx%WW; int r2=idx/WW; int oy=r2%HH; int b=r2/HH;
            float acc=bias0;
            for(int ic=0;ic<16;ic++){
                const float* ip=d_dx2up+((size_t)(b*16+ic))*NN;
#pragma unroll
                for(int ky=0;ky<3;ky++){
                    int iy=min(max(oy-1+ky,0),HH-1);
#pragma unroll
                    for(int kx=0;kx<3;kx++){
                        int ix=min(max(ox-1+kx,0),WW-1);
                        acc=fmaf(ip[iy*WW+ix], s_wt[(ic*3+ky)*3+kx], acc);
                    }
                }
            }
            float cf=0.5f*(tanhf(acc)+1.0f);
            d_conf[idx]=cf;
            lmax=fmaxf(lmax,cf);
            // raw splat (conf unscaled; divide by cmax in prep)
            int pix=idx - ((idx>=NN)? NN:0);
            int b2_=(idx>=NN);
            int h=d_pixh[idx];
            int a=d_cell2act[b2_*TT+h];
            d_pixa[idx]=a;
            int base=b2_*NN+a;
            atomicAdd(&d_cnt[base],1.0f);
            atomicAdd(&d_ws[base],cf);
            atomicAdd(&d_b4[base].x, cf*pred[(size_t)(b2_*3+0)*NN+pix]);
            atomicAdd(&d_b4[base].y, cf*pred[(size_t)(b2_*3+1)*NN+pix]);
            atomicAdd(&d_b4[base].z, cf*pred[(size_t)(b2_*3+2)*NN+pix]);
        }
        blockMaxAtomic(lmax,&d_cmaxU);
    }
    gridbar();

    // ================= P10..19: bistochastization x10 =================
    for(int it=0;it<10;it++){
        const float* src = (it&1)? d_nB : d_nA;
        float*       dst = (it&1)? d_nA : d_nB;
        for(int w=tid;w<BB*NN;w+=T){
            int b=(w>=NN); int a=w-(b?NN:0);
            if(a<d_Mcnt[b]){
                int base=b*NN+a;
                float v=src[base];
                float s=10.0f*v;
#pragma unroll
                for(int k=0;k<10;k++){
                    int id=d_nbr[k*BBNN+base];
                    if(id>=0) s+=src[b*NN+id];
                }
                dst[base]=sqrtf(v*d_cnt[base]/(s+1e-12f));
            }
        }
        gridbar();
    }

    // ================= P20: prep (scale ws/b by cmax here) =================
    {
        float cmax=fmaxf(__uint_as_float(d_cmaxU),1e-5f);
        for(int w=tid;w<BB*NN;w+=T){
            int b=(w>=NN); int a=w-(b?NN:0);
            if(a<d_Mcnt[b]){
                int base=b*NN+a;
                float n=d_nA[base];
                float s=10.0f*n;
#pragma unroll
                for(int k=0;k<10;k++){
                    int id=d_nbr[k*BBNN+base];
                    if(id>=0){
                        float nk=d_nA[b*NN+id];
                        s+=nk;
                        d_ew[k*BBNN+base]=200.0f*n*nk;
                    }
                }
                float mm=n*s;
                float ws=d_ws[base]/cmax;
                d_ws[base]=ws;
                float dg=200.0f*(mm-10.0f*n*n)+ws;
                d_diag[base]=dg;
                d_minv[base]=1.0f/fmaxf(dg,1e-5f);
                float4 bb=d_b4[base];
                bb.x/=cmax; bb.y/=cmax; bb.z/=cmax;
                d_b4[base]=bb;
                float inv=ws+1e-12f;
                d_x4[base]=make_float4(bb.x/inv,bb.y/inv,bb.z/inv,0.f);
            }
        }
    }
    gridbar();

    // ================= P21: CG init =================
    {
        float acc[6]={0,0,0,0,0,0};
        for(int w=tid;w<BB*NN;w+=T){
            int b=(w>=NN); int a=w-(b?NN:0);
            if(a<d_Mcnt[b]){
                int base=b*NN+a;
                float4 x=d_x4[base];
                float t0=0.f,t1=0.f,t2=0.f;
#pragma unroll
                for(int k=0;k<10;k++){
                    int id=d_nbr[k*BBNN+base];
                    if(id>=0){
                        float e=d_ew[k*BBNN+base];
                        float4 q=d_x4[b*NN+id];
                        t0=fmaf(e,q.x,t0); t1=fmaf(e,q.y,t1); t2=fmaf(e,q.z,t2);
                    }
                }
                float dg=d_diag[base];
                float A0=dg*x.x-t0, A1=dg*x.y-t1, A2=dg*x.z-t2;
                float4 bb=d_b4[base];
                float r0=bb.x-A0, r1=bb.y-A1, r2=bb.z-A2;
                float mi=d_minv[base];
                float z0=mi*r0, z1=mi*r1, z2=mi*r2;
                d_r4[base]=make_float4(r0,r1,r2,0.f);
                d_z4[base]=make_float4(z0,z1,z2,0.f);
                d_p4[base]=make_float4(z0,z1,z2,0.f);
                int c=b*3;
                acc[c+0]+=r0*z0; acc[c+1]+=r1*z1; acc[c+2]+=r2*z2;
            }
        }
        slotAdd6f(acc, d_rzS[0]);
    }
    gridbar();

    // ================= CG iterations =================
    for(int it=0;it<12;it++){
        // A-phase
        {
            float acc[6]={0,0,0,0,0,0};
            for(int w=tid;w<BB*NN;w+=T){
                int b=(w>=NN); int a=w-(b?NN:0);
                if(a<d_Mcnt[b]){
                    int base=b*NN+a;
                    float4 p=d_p4[base];
                    float t0=0.f,t1=0.f,t2=0.f;
#pragma unroll
                    for(int k=0;k<10;k++){
                        int id=d_nbr[k*BBNN+base];
                        if(id>=0){
                            float e=d_ew[k*BBNN+base];
                            float4 q=d_p4[b*NN+id];
                            t0=fmaf(e,q.x,t0); t1=fmaf(e,q.y,t1); t2=fmaf(e,q.z,t2);
                        }
                    }
                    float dg=d_diag[base];
                    float A0=dg*p.x-t0, A1=dg*p.y-t1, A2=dg*p.z-t2;
                    d_Ap4[base]=make_float4(A0,A1,A2,0.f);
                    int c=b*3;
                    acc[c+0]+=p.x*A0; acc[c+1]+=p.y*A1; acc[c+2]+=p.z*A2;
                }
            }
            slotAdd6f(acc, d_papS[it]);
        }
        gridbar();

        // U1
        {
            if(threadIdx.x<6)
                s_alpha[threadIdx.x]=(float)d_rzS[it][threadIdx.x]/((float)d_papS[it][threadIdx.x]+1e-12f);
            __syncthreads();
            float acc[6]={0,0,0,0,0,0};
            for(int w=tid;w<BB*NN;w+=T){
                int b=(w>=NN); int a=w-(b?NN:0);
                if(a<d_Mcnt[b]){
                    int base=b*NN+a;
                    int c=b*3;
                    float al0=s_alpha[c+0], al1=s_alpha[c+1], al2=s_alpha[c+2];
                    float4 p=d_p4[base], Ap=d_Ap4[base], x=d_x4[base], r=d_r4[base];
                    x.x+=al0*p.x; x.y+=al1*p.y; x.z+=al2*p.z;
                    r.x-=al0*Ap.x; r.y-=al1*Ap.y; r.z-=al2*Ap.z;
                    float mi=d_minv[base];
                    float z0=mi*r.x, z1=mi*r.y, z2=mi*r.z;
                    d_x4[base]=x; d_r4[base]=r;
                    d_z4[base]=make_float4(z0,z1,z2,0.f);
                    acc[c+0]+=r.x*z0; acc[c+1]+=r.y*z1; acc[c+2]+=r.z*z2;
                }
            }
            slotAdd6f(acc, d_rzS[it+1]);
        }
        gridbar();

        // U2 (skipped for final iteration)
        if(it<11){
            if(threadIdx.x<6)
                s_beta[threadIdx.x]=(float)d_rzS[it+1][threadIdx.x]/((float)d_rzS[it][threadIdx.x]+1e-12f);
            __syncthreads();
            for(int w=tid;w<BB*NN;w+=T){
                int b=(w>=NN); int a=w-(b?NN:0);
                if(a<d_Mcnt[b]){
                    int base=b*NN+a;
                    int c=b*3;
                    float4 z=d_z4[base], p=d_p4[base];
                    p.x=z.x+s_beta[c+0]*p.x;
                    p.y=z.y+s_beta[c+1]*p.y;
                    p.z=z.z+s_beta[c+2]*p.z;
                    d_p4[base]=p;
                }
            }
            gridbar();
        }
    }

    // ================= output =================
    {
        float cmax=fmaxf(__uint_as_float(d_cmaxU),1e-5f);
        for(int w=tid;w<BB*NN;w+=T){
            int b=(w>=NN); int pix=w-(b?NN:0);
            int a=d_pixa[w];
            float4 x=d_x4[b*NN+a];
            out[(size_t)(b*3+0)*NN+pix]=x.x;
            out[(size_t)(b*3+1)*NN+pix]=x.y;
            out[(size_t)(b*3+2)*NN+pix]=x.z;
            out[(size_t)BB*3*NN + w]=d_conf[w]/cmax;
        }
    }
}

// ------------------------- host -------------------------
extern "C" void kernel_launch(void* const* d_in, const int* in_sizes, int n_in,
                              void* d_out, int out_size){
    const float* image  =(const float*)d_in[0];
    const float* feature=(const float*)d_in[1];
    const float* pred   =(const float*)d_in[2];
    const float* w1 =(const float*)d_in[3];  const float* b1 =(const float*)d_in[4];
    const float* g1 =(const float*)d_in[5];  const float* be1=(const float*)d_in[6];
    const float* w2 =(const float*)d_in[7];  const float* b2 =(const float*)d_in[8];
    const float* g2 =(const float*)d_in[9];  const float* be2=(const float*)d_in[10];
    const float* wd1=(const float*)d_in[11]; const float* bd1=(const float*)d_in[12];
    const float* gd1=(const float*)d_in[13]; const float* bed1=(const float*)d_in[14];
    const float* wd2=(const float*)d_in[15]; const float* bd2=(const float*)d_in[16];
    const float* gd2=(const float*)d_in[17]; const float* bed2=(const float*)d_in[18];
    const float* wf =(const float*)d_in[19]; const float* bf =(const float*)d_in[20];
    float* out=(float*)d_out;

    int sm=0; cudaDeviceGetAttribute(&sm, cudaDevAttrMultiProcessorCount, 0);
    int occ=0; cudaOccupancyMaxActiveBlocksPerMultiprocessor(&occ, k_all, 512, 0);
    if(occ<1) occ=1;
    int G = sm*occ;
    if(G>MAXG) G=MAXG;
    G &= ~7;
    if(G<8) G=8;

    k_all<<<G,512>>>(image,feature,pred,
                     w1,b1,g1,be1, w2,b2,g2,be2,
                     wd1,bd1,gd1,bed1, wd2,bd2,gd2,bed2,
                     wf,bf, out);
}

// round 16
// speedup vs baseline: 1.0980x; 1.0980x over previous
#include <cuda_runtime.h>
#include <math.h>

#define BB 2
#define HH 384
#define WW 512
#define NN (HH*WW)          // 196608 pixels
#define BBNN (BB*NN)
#define TT (1<<20)
#define TMASK (TT-1)
#define H1 192
#define W1 256
#define H2 96
#define W2 128
#define MAXG 1024

// ------------------------- device scratch -------------------------
__device__ float d_x1[BB*16*H1*W1];
__device__ float d_x2[BB*16*H2*W2];
__device__ float d_dx1[BB*16*H2*W2];
__device__ float d_catb[BB*32*H1*W1];
__device__ float d_dx2[BB*16*H1*W1];
__device__ float d_dx2up[BB*16*NN];
__device__ float d_conf[BB*NN];

__device__ unsigned d_simgU[BB];
__device__ unsigned d_sfeatU[BB];
__device__ unsigned d_cmaxU;
__device__ double   d_gnS[4][8];

__device__ int       d_pixh[BB*NN];
__device__ int       d_pixa[BB*NN];
__device__ long long d_pixkey[BB*NN];
__device__ int       d_winner[BB*TT];
__device__ unsigned long long d_ctabP[BB*TT];
__device__ int       d_cell2act[BB*TT];
__device__ int       d_actcell[BB*NN];
__device__ int       d_Mcnt[BB];
__device__ int       d_bc0[MAXG];
__device__ int       d_bc1[MAXG];
// SoA: [k][cellbase]
__device__ int       d_nbr[10*BBNN];
__device__ float     d_ew[10*BBNN];

__device__ float  d_cnt[BB*NN];
__device__ float  d_ws[BB*NN];
__device__ float  d_nA[BB*NN];
__device__ float  d_nB[BB*NN];
__device__ float  d_diag[BB*NN];
__device__ float  d_minv[BB*NN];
__device__ float4 d_b4[BB*NN];
__device__ float4 d_x4[BB*NN];
__device__ float4 d_r4[BB*NN];
__device__ float4 d_z4[BB*NN];
__device__ float4 d_p4[BB*NN];
__device__ float4 d_Ap4[BB*NN];

__device__ double d_rzS[13][8];
__device__ double d_papS[12][8];

// barrier state (self-cleaning across graph replays)
__device__ unsigned d_sub[8];
__device__ unsigned d_root;
__device__ volatile unsigned d_phase;

// ------------------------- helpers -------------------------
__device__ __forceinline__ void gridbar(){
    __syncthreads();
    if(threadIdx.x==0){
        __threadfence();
        unsigned gen = d_phase;
        unsigned G = gridDim.x;
        unsigned g = blockIdx.x & 7u;
        unsigned gsz = (G - g + 7u) >> 3;
        unsigned t = atomicInc(&d_sub[g], gsz-1u);
        if(t == gsz-1u){
            unsigned r = atomicInc(&d_root, 7u);
            if(r == 7u){
                __threadfence();
                d_phase = gen+1u;
            }
        }
        while(d_phase == gen){ __nanosleep(64); }
    }
    __syncthreads();
    __threadfence();
}

__device__ __forceinline__ void slotAdd8f(const float* acc, double* slot){
    __shared__ float s8[16][8];
    int wp=threadIdx.x>>5, ln=threadIdx.x&31;
#pragma unroll
    for(int c=0;c<8;c++){
        float v=acc[c];
        for(int off=16;off;off>>=1) v+=__shfl_down_sync(0xffffffffu,v,off);
        if(ln==0) s8[wp][c]=v;
    }
    __syncthreads();
    if(threadIdx.x<8){
        double s=0; int nw=blockDim.x>>5;
        for(int w=0;w<nw;w++) s+=(double)s8[w][threadIdx.x];
        atomicAdd(&slot[threadIdx.x], s);
    }
    __syncthreads();
}

__device__ __forceinline__ void slotAdd6f(const float* acc, double* slot){
    __shared__ float s6[16][6];
    int wp=threadIdx.x>>5, ln=threadIdx.x&31;
#pragma unroll
    for(int c=0;c<6;c++){
        float v=acc[c];
        for(int off=16;off;off>>=1) v+=__shfl_down_sync(0xffffffffu,v,off);
        if(ln==0) s6[wp][c]=v;
    }
    __syncthreads();
    if(threadIdx.x<6){
        double s=0; int nw=blockDim.x>>5;
        for(int w=0;w<nw;w++) s+=(double)s6[w][threadIdx.x];
        atomicAdd(&slot[threadIdx.x], s);
    }
    __syncthreads();
}

__device__ __forceinline__ void blockMaxAtomic(float v, unsigned* slot){
    __shared__ float sm[16];
    int wp=threadIdx.x>>5, ln=threadIdx.x&31;
    for(int off=16;off;off>>=1) v=fmaxf(v,__shfl_down_sync(0xffffffffu,v,off));
    if(ln==0) sm[wp]=v;
    __syncthreads();
    if(threadIdx.x==0){
        float m=0.f; int nw=blockDim.x>>5;
        for(int w=0;w<nw;w++) m=fmaxf(m,sm[w]);
        atomicMax(slot, __float_as_uint(m));
    }
    __syncthreads();
}

__device__ __forceinline__ void prep_gn(int layer,int HW,const float* __restrict__ gam,
                                        const float* __restrict__ bet,float* s_misc,int off){
    if(threadIdx.x<4){
        double s=d_gnS[layer][threadIdx.x*2], q=d_gnS[layer][threadIdx.x*2+1];
        double n=8.0*(double)HW;
        double mean=s/n, var=q/n-mean*mean;
        s_misc[off+threadIdx.x]=(float)mean;
        s_misc[off+4+threadIdx.x]=(float)(1.0/sqrt(var+1e-5));
    }
    if(threadIdx.x>=32&&threadIdx.x<48) s_misc[off+8+(threadIdx.x-32)]=gam[threadIdx.x-32];
    if(threadIdx.x>=64&&threadIdx.x<80) s_misc[off+24+(threadIdx.x-64)]=bet[threadIdx.x-64];
}

__device__ __forceinline__ float gn_apply(float raw,int b,int c,const float* s_misc,int off){
    int grp=b*2+(c>>3);
    float v=(raw-s_misc[off+grp])*s_misc[off+4+grp]*s_misc[off+8+c]+s_misc[off+24+c];
    return fmaxf(v,0.0f);
}

template<int INMODE,int IC>
__device__ __forceinline__ float rd(const float* __restrict__ in,
                                    const float* __restrict__ image,
                                    const float* __restrict__ pred,
                                    const float* s_misc,int b,int c,int iy,int ix,int IH,int IW){
    if(INMODE==1){
        size_t off=((size_t)(b*3+(c%3))*IH+iy)*IW+ix;
        return (c<3)? image[off]/s_misc[80+b] : pred[off];
    }
    float raw=in[((size_t)(b*IC+c)*IH+iy)*IW+ix];
    if(INMODE==2) return gn_apply(raw,b,c,s_misc,0);
    return raw;
}

// conv phase: 1 pixel × OCB output channels per item; fp32 GN partials
template<int IC,int OC,int OCB,int K,int S,bool EDGE,int INMODE,int GNIN,int GNOUT>
__device__ void conv_ph(const float* __restrict__ in,const float* __restrict__ image,
                        const float* __restrict__ pred,
                        int IH,int IW,int OH,int OW,
                        const float* __restrict__ wt,const float* __restrict__ bias,
                        int inHW,const float* __restrict__ gamIn,const float* __restrict__ betIn,
                        float* __restrict__ outp,
                        float* s_wt,float* s_misc,int T,int tid){
    if(INMODE==2) prep_gn(GNIN,inHW,gamIn,betIn,s_misc,0);
    if(INMODE==1){
        if(threadIdx.x<BB){
            float m=__uint_as_float(d_simgU[threadIdx.x]);
            s_misc[80+threadIdx.x]=fminf(fmaxf(m,1e-5f),1.0f);
        }
    }
    for(int i=threadIdx.x;i<OC*IC*K*K;i+=blockDim.x){
        int oc=i/(IC*K*K); int rest=i-oc*IC*K*K;
        s_wt[rest*OC+oc]=wt[i];
    }
    __syncthreads();

    float gacc[8]={0,0,0,0,0,0,0,0};
    const int NPX = BB*OH*OW;
    const int nog = OC/OCB;
    for(int idx=tid; idx<NPX*nog; idx+=T){
        int px = idx % NPX;
        int og = idx / NPX;
        int ox=px%OW; int r2=px/OW; int oy=r2%OH; int b=r2/OH;
        float a[OCB];
#pragma unroll
        for(int j=0;j<OCB;j++) a[j]=bias[og*OCB+j];
        for(int ic=0;ic<IC;ic++){
#pragma unroll
            for(int ky=0;ky<K;ky++){
                int iy=oy*S-1+ky;
                if(EDGE) iy=min(max(iy,0),IH-1);
                else if(iy<0||iy>=IH) continue;
#pragma unroll
                for(int kx=0;kx<K;kx++){
                    int ix=ox*S-1+kx;
                    float v;
                    if(EDGE){
                        int jx=min(max(ix,0),IW-1);
                        v=rd<INMODE,IC>(in,image,pred,s_misc,b,ic,iy,jx,IH,IW);
                    }else{
                        if(ix<0||ix>=IW) continue;
                        v=rd<INMODE,IC>(in,image,pred,s_misc,b,ic,iy,ix,IH,IW);
                    }
                    const float* w=&s_wt[((ic*K+ky)*K+kx)*OC + og*OCB];
#pragma unroll
                    for(int j=0;j<OCB;j++) a[j]=fmaf(v,w[j],a[j]);
                }
            }
        }
#pragma unroll
        for(int j=0;j<OCB;j++){
            int oc=og*OCB+j;
            outp[((size_t)(b*OC+oc)*OH+oy)*OW+ox]=a[j];
            if(GNOUT>=0){
                float dd=a[j];
                int slot=(b<<1)|(oc>>3);
                gacc[slot*2]+=dd; gacc[slot*2+1]+=dd*dd;
            }
        }
    }
    if(GNOUT>=0) slotAdd8f(gacc,d_gnS[GNOUT]);
}

__device__ __forceinline__ void pix_coords(const float* __restrict__ feature,int b,int pix,
                                           float s,int* c){
    float r  = (feature[(size_t)(b*3+0)*NN+pix]/s)*255.0f;
    float g  = (feature[(size_t)(b*3+1)*NN+pix]/s)*255.0f;
    float bl = (feature[(size_t)(b*3+2)*NN+pix]/s)*255.0f;
    int i = pix/WW, j = pix - i*WW;
    float Y = fmaf(bl,0.114f,    fmaf(g,0.587f,    r*0.299f));
    float U = fmaf(bl,0.5f,      fmaf(g,-0.331264f,r*(-0.168736f)))+128.0f;
    float V = fmaf(bl,-0.081312f,fmaf(g,-0.418688f,r*0.5f))+128.0f;
    c[0]=(int)floorf((float)j/7.0f);
    c[1]=(int)floorf((float)i/7.0f);
    c[2]=(int)floorf(Y*0.125f);
    c[3]=(int)floorf(U*0.5f);
    c[4]=(int)floorf(V*0.5f);
}

__device__ __forceinline__ int hash5i(const int* c){
    unsigned s = (unsigned)c[0]*73856093u + (unsigned)c[1]*19349663u + (unsigned)c[2]*83492791u
               + (unsigned)c[3]*49979687u + (unsigned)c[4]*24036583u;
    return (int)(s & (unsigned)TMASK);
}

__device__ __forceinline__ unsigned long long pack5(const int* c){
    unsigned long long k=0;
#pragma unroll
    for(int d=0;d<5;d++) k |= ((unsigned long long)(unsigned)(c[d]+1)) << (12*d);
    return k;
}

// ------------------------- THE kernel -------------------------
__global__ void __launch_bounds__(512,2) k_all(
    const float* __restrict__ image,const float* __restrict__ feature,const float* __restrict__ pred,
    const float* __restrict__ w1,const float* __restrict__ b1,const float* __restrict__ g1,const float* __restrict__ be1,
    const float* __restrict__ w2,const float* __restrict__ b2,const float* __restrict__ g2,const float* __restrict__ be2,
    const float* __restrict__ wd1,const float* __restrict__ bd1,const float* __restrict__ gd1,const float* __restrict__ bed1,
    const float* __restrict__ wd2,const float* __restrict__ bd2,const float* __restrict__ gd2,const float* __restrict__ bed2,
    const float* __restrict__ wf,const float* __restrict__ bf,
    float* __restrict__ out)
{
    const int T   = blockDim.x*gridDim.x;
    const int tid = blockIdx.x*blockDim.x + threadIdx.x;
    const int G   = gridDim.x;

    __shared__ float s_wt[4608];
    __shared__ float s_misc[128];
    __shared__ float s_alpha[6], s_beta[6];
    __shared__ int s_w0[16], s_w1[16];
    __shared__ int s_base0, s_base1, s_off0, s_off1, s_tot0, s_tot1;

    const unsigned PRIME[5]={73856093u,19349663u,83492791u,49979687u,24036583u};
    const int nsteps = (BBNN + G*512 - 1)/(G*512);
    const int chunk  = nsteps*512;

    // ================= P0: clears + input maxes (fused) =================
    for(int i=tid;i<BB*TT;i+=T) d_winner[i]=-1;
    for(int i=tid;i<BB*TT;i+=T) d_ctabP[i]=0xFFFFFFFFFFFFFFFFULL;
    if(tid<BB) d_Mcnt[tid]=0;
    if(tid>=8 && tid<8+32)   ((double*)d_gnS)[tid-8]=0.0;
    if(tid>=64 && tid<64+104)((double*)d_rzS)[tid-64]=0.0;
    if(tid>=192 && tid<192+96)((double*)d_papS)[tid-192]=0.0;
    if(tid==300) d_cmaxU=0u;
    if(tid>=301&&tid<301+BB) d_simgU[tid-301]=0u;
    if(tid>=303&&tid<303+BB) d_sfeatU[tid-303]=0u;
    for(int i=tid;i<BB*NN;i+=T){
        d_cnt[i]=0.f; d_ws[i]=0.f;
        d_b4[i]=make_float4(0.f,0.f,0.f,0.f);
    }
    {
        float mi0=0.f,mi1=0.f,mf0=0.f,mf1=0.f;
        for(int i=tid;i<BB*3*NN;i+=T){
            float v=image[i], w=feature[i];
            if(i<3*NN){ mi0=fmaxf(mi0,v); mf0=fmaxf(mf0,w); }
            else      { mi1=fmaxf(mi1,v); mf1=fmaxf(mf1,w); }
        }
        blockMaxAtomic(mi0,&d_simgU[0]);
        blockMaxAtomic(mi1,&d_simgU[1]);
        blockMaxAtomic(mf0,&d_sfeatU[0]);
        blockMaxAtomic(mf1,&d_sfeatU[1]);
    }
    gridbar();

    // ================= P2: conv1 + hash =================
    conv_ph<6,16,8,4,2,true,1,0,0>(nullptr,image,pred,HH,WW,H1,W1,w1,b1,
                                   0,nullptr,nullptr,d_x1,s_wt,s_misc,T,tid);
    for(int w=tid;w<BB*NN;w+=T){
        int b=(w>=NN); int pix=w-(b?NN:0);
        float sf=fminf(fmaxf(__uint_as_float(d_sfeatU[b]),1e-5f),1.0f);
        int c[5]; pix_coords(feature,b,pix,sf,c);
        int h=hash5i(c);
        d_pixh[w]=h;
        d_pixkey[w]=(long long)pack5(c);
        atomicMax(&d_winner[b*TT+h],pix);
    }
    gridbar();

    // ================= P3: conv2 + ctab =================
    conv_ph<16,16,4,4,2,true,2,0,1>(d_x1,nullptr,nullptr,H1,W1,H2,W2,w2,b2,
                                    H1*W1,g1,be1,d_x2,s_wt,s_misc,T,tid);
    for(int w=tid;w<BB*NN;w+=T){
        int b=(w>=NN); int pix=w-(b?NN:0);
        int h=d_pixh[w];
        if(d_winner[b*TT+h]==pix)
            d_ctabP[b*TT+h]=(unsigned long long)d_pixkey[w];
    }
    gridbar();

    // ================= P4: convd1 + ordered-compact counts =================
    conv_ph<16,16,4,3,1,false,2,1,2>(d_x2,nullptr,nullptr,H2,W2,H2,W2,wd1,bd1,
                                     H2*W2,g2,be2,d_dx1,s_wt,s_misc,T,tid);
    {
        int start=blockIdx.x*chunk;
        int c0=0,c1=0;
        for(int o=threadIdx.x;o<chunk;o+=512){
            int w=start+o;
            if(w<BBNN){
                int b=(w>=NN); int pix=w-(b?NN:0);
                int h=d_pixh[w];
                if(d_winner[b*TT+h]==pix){ if(b) c1++; else c0++; }
            }
        }
        int wp=threadIdx.x>>5, ln=threadIdx.x&31;
        for(int off=16;off;off>>=1){
            c0+=__shfl_down_sync(0xffffffffu,c0,off);
            c1+=__shfl_down_sync(0xffffffffu,c1,off);
        }
        if(ln==0){ s_w0[wp]=c0; s_w1[wp]=c1; }
        __syncthreads();
        if(threadIdx.x==0){
            int t0=0,t1=0;
            for(int j=0;j<16;j++){ t0+=s_w0[j]; t1+=s_w1[j]; }
            d_bc0[blockIdx.x]=t0; d_bc1[blockIdx.x]=t1;
        }
        __syncthreads();
    }
    gridbar();

    // ================= P4b: ordered-compact assignment =================
    {
        int wp=threadIdx.x>>5, ln=threadIdx.x&31;
        if(wp==0){
            int o0=0,t0=0;
            for(int j=ln;j<G;j+=32){ int v=d_bc0[j]; t0+=v; if(j<blockIdx.x) o0+=v; }
            for(int off=16;off;off>>=1){
                o0+=__shfl_down_sync(0xffffffffu,o0,off);
                t0+=__shfl_down_sync(0xffffffffu,t0,off);
            }
            if(ln==0){ s_off0=o0; s_tot0=t0; }
        }
        if(wp==1){
            int o1=0,t1=0;
            for(int j=ln;j<G;j+=32){ int v=d_bc1[j]; t1+=v; if(j<blockIdx.x) o1+=v; }
            for(int off=16;off;off>>=1){
                o1+=__shfl_down_sync(0xffffffffu,o1,off);
                t1+=__shfl_down_sync(0xffffffffu,t1,off);
            }
            if(ln==0){ s_off1=o1; s_tot1=t1; }
        }
        __syncthreads();
        if(blockIdx.x==0&&threadIdx.x==0){ d_Mcnt[0]=s_tot0; d_Mcnt[1]=s_tot1; }
        if(threadIdx.x==0){ s_base0=s_off0; s_base1=s_off1; }
        __syncthreads();
        int start=blockIdx.x*chunk;
        for(int s=0;s<nsteps;s++){
            int w=start+s*512+threadIdx.x;
            int b=0,h=0; bool win=false;
            if(w<BBNN){
                b=(w>=NN); int pix=w-(b?NN:0);
                h=d_pixh[w];
                win=(d_winner[b*TT+h]==pix);
            }
            unsigned m0=__ballot_sync(0xffffffffu, win && b==0);
            unsigned m1=__ballot_sync(0xffffffffu, win && b==1);
            if(ln==0){ s_w0[wp]=__popc(m0); s_w1[wp]=__popc(m1); }
            __syncthreads();
            int p0=0,p1=0,tt0=0,tt1=0;
            for(int j=0;j<16;j++){
                int v0=s_w0[j], v1=s_w1[j];
                if(j<wp){ p0+=v0; p1+=v1; }
                tt0+=v0; tt1+=v1;
            }
            if(win){
                unsigned lm=(1u<<ln)-1u;
                int a = b? (s_base1+p1+__popc(m1&lm)) : (s_base0+p0+__popc(m0&lm));
                d_cell2act[b*TT+h]=a;
                d_actcell[b*NN+a]=h;
            }
            __syncthreads();
            if(threadIdx.x==0){ s_base0+=tt0; s_base1+=tt1; }
            __syncthreads();
        }
    }
    gridbar();

    // ================= P5: catb + nbr build (SoA) =================
    prep_gn(2,H2*W2,gd1,bed1,s_misc,0);
    prep_gn(0,H1*W1,g1,be1,s_misc,40);
    __syncthreads();
    for(int i=tid;i<BB*16*H1*W1;i+=T){
        int ox=i%W1; int r2=i/W1; int oy=r2%H1; r2/=H1;
        int c=r2%16; int b=r2/16;
        float cy=oy*0.5f-0.25f, cx=ox*0.5f-0.25f;
        int y0=(int)floorf(cy); float fy=cy-(float)y0;
        int x0=(int)floorf(cx); float fx=cx-(float)x0;
        int y1=min(y0+1,H2-1), x1=min(x0+1,W2-1);
        y0=max(y0,0); x0=max(x0,0);
        const float* ip=d_dx1+((size_t)(b*16+c))*H2*W2;
        float v00=gn_apply(ip[y0*W2+x0],b,c,s_misc,0);
        float v01=gn_apply(ip[y0*W2+x1],b,c,s_misc,0);
        float v10=gn_apply(ip[y1*W2+x0],b,c,s_misc,0);
        float v11=gn_apply(ip[y1*W2+x1],b,c,s_misc,0);
        float top=v00+fx*(v01-v00), bot=v10+fx*(v11-v10);
        d_catb[((size_t)(b*32+c)*H1+oy)*W1+ox]=top+fy*(bot-top);
    }
    for(int i=tid;i<BB*16*H1*W1;i+=T){
        int p=i%(H1*W1); int c=(i/(H1*W1))&15; int b=i/(16*H1*W1);
        float v=gn_apply(d_x1[((size_t)(b*16+c))*H1*W1+p],b,c,s_misc,40);
        d_catb[((size_t)(b*32+16+c))*H1*W1+p]=v;
    }
    for(int w=tid;w<BB*NN;w+=T){
        int b=(w>=NN); int a=w-(b?NN:0);
        if(a<d_Mcnt[b]){
            int cell=d_actcell[b*NN+a];
            unsigned long long key=d_ctabP[b*TT+cell];
            int base=b*NN+a;
            int k=0;
#pragma unroll
            for(int d=0;d<5;d++){
#pragma unroll
                for(int o=0;o<2;o++){
                    unsigned nh = ((unsigned)cell + (o? PRIME[d] : (0u-PRIME[d]))) & (unsigned)TMASK;
                    unsigned long long keyN = o? key+(1ULL<<(12*d)) : key-(1ULL<<(12*d));
                    int res=-1;
                    if(d_ctabP[b*TT+(int)nh]==keyN) res=d_cell2act[b*TT+(int)nh];
                    d_nbr[k*BBNN+base]=res;
                    k++;
                }
            }
            d_nA[base]=1.0f;
        }
    }
    gridbar();

    // ================= P6: convd2 =================
    conv_ph<32,16,8,3,1,false,0,0,3>(d_catb,nullptr,nullptr,H1,W1,H1,W1,wd2,bd2,
                                     0,nullptr,nullptr,d_dx2,s_wt,s_misc,T,tid);
    gridbar();

    // ================= P7: resize2 =================
    prep_gn(3,H1*W1,gd2,bed2,s_misc,0);
    __syncthreads();
    for(int i=tid;i<BB*16*NN;i+=T){
        int ox=i%WW; int r2=i/WW; int oy=r2%HH; r2/=HH;
        int c=r2%16; int b=r2/16;
        float cy=oy*0.5f-0.25f, cx=ox*0.5f-0.25f;
        int y0=(int)floorf(cy); float fy=cy-(float)y0;
        int x0=(int)floorf(cx); float fx=cx-(float)x0;
        int y1=min(y0+1,H1-1), x1=min(x0+1,W1-1);
        y0=max(y0,0); x0=max(x0,0);
        const float* ip=d_dx2+((size_t)(b*16+c))*H1*W1;
        float v00=gn_apply(ip[y0*W1+x0],b,c,s_misc,0);
        float v01=gn_apply(ip[y0*W1+x1],b,c,s_misc,0);
        float v10=gn_apply(ip[y1*W1+x0],b,c,s_misc,0);
        float v11=gn_apply(ip[y1*W1+x1],b,c,s_misc,0);
        float top=v00+fx*(v01-v00), bot=v10+fx*(v11-v10);
        d_dx2up[((size_t)(b*16+c)*HH+oy)*WW+ox]=top+fy*(bot-top);
    }
    gridbar();

    // ================= P8: convf + conf max + RAW splat =================
    for(int i=threadIdx.x;i<144;i+=blockDim.x) s_wt[i]=wf[i];
    __syncthreads();
    {
        float bias0=bf[0];
        float lmax=0.f;
        for(int idx=tid; idx<BB*NN; idx+=T){
            int ox=idx%WW; int r2=idx/WW; int oy=r2%HH; int b=r2/HH;
            float acc=bias0;
            for(int ic=0;ic<16;ic++){
                const float* ip=d_dx2up+((size_t)(b*16+ic))*NN;
#pragma unroll
                for(int ky=0;ky<3;ky++){
                    int iy=min(max(oy-1+ky,0),HH-1);
#pragma unroll
                    for(int kx=0;kx<3;kx++){
                        int ix=min(max(ox-1+kx,0),WW-1);
                        acc=fmaf(ip[iy*WW+ix], s_wt[(ic*3+ky)*3+kx], acc);
                    }
                }
            }
            float cf=0.5f*(tanhf(acc)+1.0f);
            d_conf[idx]=cf;
            lmax=fmaxf(lmax,cf);
            int pix=idx - ((idx>=NN)? NN:0);
            int b2_=(idx>=NN);
            int h=d_pixh[idx];
            int a=d_cell2act[b2_*TT+h];
            d_pixa[idx]=a;
            int base=b2_*NN+a;
            atomicAdd(&d_cnt[base],1.0f);
            atomicAdd(&d_ws[base],cf);
            atomicAdd(&d_b4[base].x, cf*pred[(size_t)(b2_*3+0)*NN+pix]);
            atomicAdd(&d_b4[base].y, cf*pred[(size_t)(b2_*3+1)*NN+pix]);
            atomicAdd(&d_b4[base].z, cf*pred[(size_t)(b2_*3+2)*NN+pix]);
        }
        blockMaxAtomic(lmax,&d_cmaxU);
    }
    gridbar();

    // ================= P10..19: bistochastization x10 =================
    for(int it=0;it<10;it++){
        const float* src = (it&1)? d_nB : d_nA;
        float*       dst = (it&1)? d_nA : d_nB;
        for(int w=tid;w<BB*NN;w+=T){
            int b=(w>=NN); int a=w-(b?NN:0);
            if(a<d_Mcnt[b]){
                int base=b*NN+a;
                float v=src[base];
                float s=10.0f*v;
#pragma unroll
                for(int k=0;k<10;k++){
                    int id=d_nbr[k*BBNN+base];
                    if(id>=0) s+=src[b*NN+id];
                }
                dst[base]=sqrtf(v*d_cnt[base]/(s+1e-12f));
            }
        }
        gridbar();
    }

    // ================= P20: prep (scale ws/b by cmax here) =================
    {
        float cmax=fmaxf(__uint_as_float(d_cmaxU),1e-5f);
        for(int w=tid;w<BB*NN;w+=T){
            int b=(w>=NN); int a=w-(b?NN:0);
            if(a<d_Mcnt[b]){
                int base=b*NN+a;
                float n=d_nA[base];
                float s=10.0f*n;
#pragma unroll
                for(int k=0;k<10;k++){
                    int id=d_nbr[k*BBNN+base];
                    if(id>=0){
                        float nk=d_nA[b*NN+id];
                        s+=nk;
                        d_ew[k*BBNN+base]=200.0f*n*nk;
                    }
                }
                float mm=n*s;
                float ws=d_ws[base]/cmax;
                d_ws[base]=ws;
                float dg=200.0f*(mm-10.0f*n*n)+ws;
                d_diag[base]=dg;
                d_minv[base]=1.0f/fmaxf(dg,1e-5f);
                float4 bb=d_b4[base];
                bb.x/=cmax; bb.y/=cmax; bb.z/=cmax;
                d_b4[base]=bb;
                float inv=ws+1e-12f;
                d_x4[base]=make_float4(bb.x/inv,bb.y/inv,bb.z/inv,0.f);
            }
        }
    }
    gridbar();

    // ================= P21: CG init =================
    {
        float acc[6]={0,0,0,0,0,0};
        for(int w=tid;w<BB*NN;w+=T){
            int b=(w>=NN); int a=w-(b?NN:0);
            if(a<d_Mcnt[b]){
                int base=b*NN+a;
                float4 x=d_x4[base];
                float t0=0.f,t1=0.f,t2=0.f;
#pragma unroll
                for(int k=0;k<10;k++){
                    int id=d_nbr[k*BBNN+base];
                    if(id>=0){
                        float e=d_ew[k*BBNN+base];
                        float4 q=d_x4[b*NN+id];
                        t0=fmaf(e,q.x,t0); t1=fmaf(e,q.y,t1); t2=fmaf(e,q.z,t2);
                    }
                }
                float dg=d_diag[base];
                float A0=dg*x.x-t0, A1=dg*x.y-t1, A2=dg*x.z-t2;
                float4 bb=d_b4[base];
                float r0=bb.x-A0, r1=bb.y-A1, r2=bb.z-A2;
                float mi=d_minv[base];
                float z0=mi*r0, z1=mi*r1, z2=mi*r2;
                d_r4[base]=make_float4(r0,r1,r2,0.f);
                d_z4[base]=make_float4(z0,z1,z2,0.f);
                d_p4[base]=make_float4(z0,z1,z2,0.f);
                int c=b*3;
                acc[c+0]+=r0*z0; acc[c+1]+=r1*z1; acc[c+2]+=r2*z2;
            }
        }
        slotAdd6f(acc, d_rzS[0]);
    }
    gridbar();

    // ================= CG iterations =================
    for(int it=0;it<12;it++){
        // A-phase
        {
            float acc[6]={0,0,0,0,0,0};
            for(int w=tid;w<BB*NN;w+=T){
                int b=(w>=NN); int a=w-(b?NN:0);
                if(a<d_Mcnt[b]){
                    int base=b*NN+a;
                    float4 p=d_p4[base];
                    float t0=0.f,t1=0.f,t2=0.f;
#pragma unroll
                    for(int k=0;k<10;k++){
                        int id=d_nbr[k*BBNN+base];
                        if(id>=0){
                            float e=d_ew[k*BBNN+base];
                            float4 q=d_p4[b*NN+id];
                            t0=fmaf(e,q.x,t0); t1=fmaf(e,q.y,t1); t2=fmaf(e,q.z,t2);
                        }
                    }
                    float dg=d_diag[base];
                    float A0=dg*p.x-t0, A1=dg*p.y-t1, A2=dg*p.z-t2;
                    d_Ap4[base]=make_float4(A0,A1,A2,0.f);
                    int c=b*3;
                    acc[c+0]+=p.x*A0; acc[c+1]+=p.y*A1; acc[c+2]+=p.z*A2;
                }
            }
            slotAdd6f(acc, d_papS[it]);
        }
        gridbar();

        // U1
        {
            if(threadIdx.x<6)
                s_alpha[threadIdx.x]=(float)d_rzS[it][threadIdx.x]/((float)d_papS[it][threadIdx.x]+1e-12f);
            __syncthreads();
            float acc[6]={0,0,0,0,0,0};
            for(int w=tid;w<BB*NN;w+=T){
                int b=(w>=NN); int a=w-(b?NN:0);
                if(a<d_Mcnt[b]){
                    int base=b*NN+a;
                    int c=b*3;
                    float al0=s_alpha[c+0], al1=s_alpha[c+1], al2=s_alpha[c+2];
                    float4 p=d_p4[base], Ap=d_Ap4[base], x=d_x4[base], r=d_r4[base];
                    x.x+=al0*p.x; x.y+=al1*p.y; x.z+=al2*p.z;
                    r.x-=al0*Ap.x; r.y-=al1*Ap.y; r.z-=al2*Ap.z;
                    float mi=d_minv[base];
                    float z0=mi*r.x, z1=mi*r.y, z2=mi*r.z;
                    d_x4[base]=x; d_r4[base]=r;
                    d_z4[base]=make_float4(z0,z1,z2,0.f);
                    acc[c+0]+=r.x*z0; acc[c+1]+=r.y*z1; acc[c+2]+=r.z*z2;
                }
            }
            slotAdd6f(acc, d_rzS[it+1]);
        }
        gridbar();

        // U2 (skipped for final iteration)
        if(it<11){
            if(threadIdx.x<6)
                s_beta[threadIdx.x]=(float)d_rzS[it+1][threadIdx.x]/((float)d_rzS[it][threadIdx.x]+1e-12f);
            __syncthreads();
            for(int w=tid;w<BB*NN;w+=T){
                int b=(w>=NN); int a=w-(b?NN:0);
                if(a<d_Mcnt[b]){
                    int base=b*NN+a;
                    int c=b*3;
                    float4 z=d_z4[base], p=d_p4[base];
                    p.x=z.x+s_beta[c+0]*p.x;
                    p.y=z.y+s_beta[c+1]*p.y;
                    p.z=z.z+s_beta[c+2]*p.z;
                    d_p4[base]=p;
                }
            }
            gridbar();
        }
    }

    // ================= output =================
    {
        float cmax=fmaxf(__uint_as_float(d_cmaxU),1e-5f);
        for(int w=tid;w<BB*NN;w+=T){
            int b=(w>=NN); int pix=w-(b?NN:0);
            int a=d_pixa[w];
            float4 x=d_x4[b*NN+a];
            out[(size_t)(b*3+0)*NN+pix]=x.x;
            out[(size_t)(b*3+1)*NN+pix]=x.y;
            out[(size_t)(b*3+2)*NN+pix]=x.z;
            out[(size_t)BB*3*NN + w]=d_conf[w]/cmax;
        }
    }
}

// ------------------------- host -------------------------
extern "C" void kernel_launch(void* const* d_in, const int* in_sizes, int n_in,
                              void* d_out, int out_size){
    const float* image  =(const float*)d_in[0];
    const float* feature=(const float*)d_in[1];
    const float* pred   =(const float*)d_in[2];
    const float* w1 =(const float*)d_in[3];  const float* b1 =(const float*)d_in[4];
    const float* g1 =(const float*)d_in[5];  const float* be1=(const float*)d_in[6];
    const float* w2 =(const float*)d_in[7];  const float* b2 =(const float*)d_in[8];
    const float* g2 =(const float*)d_in[9];  const float* be2=(const float*)d_in[10];
    const float* wd1=(const float*)d_in[11]; const float* bd1=(const float*)d_in[12];
    const float* gd1=(const float*)d_in[13]; const float* bed1=(const float*)d_in[14];
    const float* wd2=(const float*)d_in[15]; const float* bd2=(const float*)d_in[16];
    const float* gd2=(const float*)d_in[17]; const float* bed2=(const float*)d_in[18];
    const float* wf =(const float*)d_in[19]; const float* bf =(const float*)d_in[20];
    float* out=(float*)d_out;

    int sm=0; cudaDeviceGetAttribute(&sm, cudaDevAttrMultiProcessorCount, 0);
    int occ=0; cudaOccupancyMaxActiveBlocksPerMultiprocessor(&occ, k_all, 512, 0);
    if(occ<1) occ=1;
    int G = sm*occ;
    if(G>MAXG) G=MAXG;
    G &= ~7;
    if(G<8) G=8;

    k_all<<<G,512>>>(image,feature,pred,
                     w1,b1,g1,be1, w2,b2,g2,be2,
                     wd1,bd1,gd1,bed1, wd2,bd2,gd2,bed2,
                     wf,bf, out);
}